// round 16
// baseline (speedup 1.0000x reference)
#include <cuda_runtime.h>
#include <cstdint>

#define B 16
#define G 128
#define P 8000
#define R 200
#define POS_CAP 66
#define NSPLIT 24
#define CHUNK 334          // 24 * 334 = 8016 >= 8000
#define NBINS 1024
#define CAND_CAP 512

// ---------------- scratch (no allocations allowed) ----------------
// All state is rewritten every launch (or only read where written) -> no init
// kernel, no cross-launch contamination, graph-replay deterministic.
__device__ unsigned long long d_part[B * NSPLIT * G];  // per-block per-g best
__device__ int d_parg[B * P];
__device__ unsigned long long d_poskeys[B * P];
__device__ unsigned long long d_negkeys[B * P];
__device__ int d_poscount[B];
__device__ int d_negcount[B];
__device__ int d_posidx[B * POS_CAP];
__device__ int d_negidx[B * R];

// ---------------- threefry2x32 (exact JAX, partitionable path) ----------
__device__ __forceinline__ uint32_t rotl32(uint32_t v, int d) {
    return (v << d) | (v >> (32 - d));
}

__device__ __forceinline__ void threefry(uint32_t k0, uint32_t k1, uint32_t x0,
                                         uint32_t x1, uint32_t& o0, uint32_t& o1) {
    uint32_t ks2 = k0 ^ k1 ^ 0x1BD11BDAu;
    x0 += k0; x1 += k1;
#define TFR(r) { x0 += x1; x1 = rotl32(x1, r); x1 ^= x0; }
    TFR(13) TFR(15) TFR(26) TFR(6)
    x0 += k1; x1 += ks2 + 1u;
    TFR(17) TFR(29) TFR(16) TFR(24)
    x0 += ks2; x1 += k0 + 2u;
    TFR(13) TFR(15) TFR(26) TFR(6)
    x0 += k0; x1 += k1 + 3u;
    TFR(17) TFR(29) TFR(16) TFR(24)
    x0 += k1; x1 += ks2 + 4u;
    TFR(13) TFR(15) TFR(26) TFR(6)
    x0 += ks2; x1 += k0 + 5u;
#undef TFR
    o0 = x0; o1 = x1;
}

__device__ __forceinline__ void batch_keys(int b, uint32_t& k1a, uint32_t& k1b,
                                           uint32_t& k2a, uint32_t& k2b) {
    uint32_t kb0, kb1;
    threefry(0u, 42u, 0u, (uint32_t)b, kb0, kb1);   // split(key(42), 16)[b]
    threefry(kb0, kb1, 0u, 0u, k1a, k1b);           // split(key_b, 2)[0]
    threefry(kb0, kb1, 0u, 1u, k2a, k2b);           // split(key_b, 2)[1]
}

// u = m * 2^-23, m = (o0^o1)>>9: strictly monotonic in m -> sort on mantissa
__device__ __forceinline__ uint32_t umant(uint32_t ka, uint32_t kb, int p) {
    uint32_t a, c;
    threefry(ka, kb, 0u, (uint32_t)p, a, c);
    return (a ^ c) >> 9;
}

__device__ __forceinline__ uint32_t ford(float f) {
    uint32_t u = __float_as_uint(f);
    return (u & 0x80000000u) ? ~u : (u | 0x80000000u);
}

// ================= K1: IoU + dual argmax + RNG keys (384 blocks) =========
__global__ __launch_bounds__(512, 3)
void k1_iou(const float* __restrict__ gt, const float* __restrict__ pr) {
    __shared__ float4 sg4[G];
    __shared__ float sga[G];
    __shared__ unsigned char sgl[G];
    __shared__ unsigned long long sbest[G];
    __shared__ int s_wcnt[4], s_woff[4], s_ng;

    int bid = blockIdx.x;
    int tid = threadIdx.x;
    int lane = tid & 31;
    int wid = tid >> 5;
    int b = bid / NSPLIT;
    int split = bid % NSPLIT;

    // GT load + order-preserving compaction of valid gts
    bool gvalid = false;
    float a0 = 0, a1 = 0, a2 = 0, a3 = 0;
    if (tid < G) {
        const float* gp = gt + ((size_t)b * G + tid) * 5;
        a0 = gp[0]; a1 = gp[1]; a2 = gp[2]; a3 = gp[3];
        gvalid = (gp[4] != 0.0f);
        sbest[tid] = 0ull;
        unsigned ball = __ballot_sync(0xFFFFFFFFu, gvalid);
        if (lane == 0) s_wcnt[wid] = __popc(ball);
    }
    __syncthreads();
    if (tid == 0) {
        int off = 0;
        for (int w = 0; w < 4; ++w) { s_woff[w] = off; off += s_wcnt[w]; }
        s_ng = off;
    }
    __syncthreads();
    if (tid < G && gvalid) {
        unsigned ball = __ballot_sync(__activemask(), true);
        int rank = s_woff[wid] + __popc(ball & ((1u << lane) - 1u));
        sg4[rank] = make_float4(a0, a1, a2, a3);
        sga[rank] = __fmul_rn(__fsub_rn(a3, a1), __fsub_rn(a2, a0));
        sgl[rank] = (unsigned char)tid;
    }
    __syncthreads();
    int ng = s_ng;

    int p = split * CHUNK + tid;
    bool act = (tid < CHUNK) && (p < P);
    float p0 = 0, p1 = 0, p2 = 0, p3 = 0, ap = 0;
    bool pv = false;
    if (act) {
        const float* pp = pr + ((size_t)b * P + p) * 5;
        p0 = pp[0]; p1 = pp[1]; p2 = pp[2]; p3 = pp[3];
        pv = (pp[4] != 0.0f);
        ap = __fmul_rn(__fsub_rn(p3, p1), __fsub_rn(p2, p0));
    }

    float best = -1.0f;
    int barg = 0;
    uint32_t wbase = (uint32_t)(split * CHUNK + (tid & ~31));

    for (int i = 0; i < ng; ++i) {
        float4 gb = sg4[i];
        float iw = fmaxf(0.0f, __fsub_rn(fminf(gb.w, p3), fmaxf(gb.y, p1)));
        float ih = fmaxf(0.0f, __fsub_rn(fminf(gb.z, p2), fmaxf(gb.x, p0)));
        float inter = __fmul_rn(iw, ih);
        float denom = __fsub_rn(__fadd_rn(sga[i], ap), inter);
        float iou = __fdiv_rn(inter, denom);
        bool valid = act && pv;
        float v = valid ? iou : -1.0f;
        if (v > best) { best = v; barg = i; }       // first-index argmax

        uint32_t fv = valid ? ford(v) : 0u;         // valid -> fv != 0
        uint32_t wmax = __reduce_max_sync(0xFFFFFFFFu, fv);
        uint32_t ball = __ballot_sync(0xFFFFFFFFu, fv == wmax && wmax != 0u);
        if (lane == 0 && ball != 0u) {
            int src = __ffs(ball) - 1;              // lowest lane = lowest p
            uint32_t plow = 0xFFFFFFFFu - (wbase + (uint32_t)src);
            atomicMax(&sbest[i],
                      (((unsigned long long)wmax) << 32) | (unsigned long long)plow);
        }
    }

    // RNG sort keys (removed-filter deferred to K2a) + parg
    if (act) {
        bool pos = (best >= 0.5f);
        uint32_t k1a, k1b, k2a, k2b;
        batch_keys(b, k1a, k1b, k2a, k2b);
        unsigned long long pk = 0ull, nk = 0ull;
        if (pv) {
            uint32_t plow = 0xFFFFFFFFu - (uint32_t)p;
            if (pos) {
                pk = (((unsigned long long)umant(k1a, k1b, p)) << 32) |
                     (unsigned long long)plow;
                d_parg[(size_t)b * P + p] = sgl[barg];
            } else {
                nk = (((unsigned long long)umant(k2a, k2b, p)) << 32) |
                     (unsigned long long)plow;
            }
        }
        size_t bp = (size_t)b * P + p;
        d_poskeys[bp] = pk;
        d_negkeys[bp] = nk;
    }

    __syncthreads();
    // partial per-g maxima, compacted index space (slots >= ng never read)
    if (tid < ng) d_part[(size_t)bid * G + tid] = sbest[tid];
}

// ===== K2a: partial-reduce, removed-filter, exact top-K (32 blocks) ======
__global__ __launch_bounds__(512, 2)
void k2a_select(const float* __restrict__ gt, float* __restrict__ miss_out) {
    __shared__ uint32_t hist[NBINS];
    __shared__ uint32_t sfx[NBINS];
    __shared__ uint32_t sfx2[NBINS];
    __shared__ unsigned long long cand[CAND_CAP];
    __shared__ uint32_t cand_p[CAND_CAP];
    __shared__ uint32_t s_rem[P / 32];          // 250 words removed-bitmap
    __shared__ unsigned char s_matched[G];
    __shared__ int s_wcnt[4], s_woff4, s_ng, s_T, s_cnt, s_kept, s_miss;

    int tid = threadIdx.x;
    int lane = tid & 31;
    int wid = tid >> 5;
    int b = blockIdx.x >> 1;
    bool isPos = ((blockIdx.x & 1) == 0);
    int K = isPos ? POS_CAP : R;
    const unsigned long long* src =
        isPos ? (d_poskeys + (size_t)b * P) : (d_negkeys + (size_t)b * P);

    // valid-gt count (ng) — defines meaningful d_part slots
    bool gvalid = false;
    if (tid < G) {
        gvalid = (gt[((size_t)b * G + tid) * 5 + 4] != 0.0f);
        unsigned ball = __ballot_sync(0xFFFFFFFFu, gvalid);
        if (lane == 0) s_wcnt[wid] = __popc(ball);
    }
    for (int i = tid; i < P / 32; i += 512) s_rem[i] = 0u;
    for (int i = tid; i < NBINS; i += 512) hist[i] = 0u;
    if (tid < G) s_matched[tid] = 0;
    if (tid == 0) { s_T = 0; s_cnt = 0; s_kept = 0; s_miss = 0; }
    __syncthreads();
    if (tid == 0) s_ng = s_wcnt[0] + s_wcnt[1] + s_wcnt[2] + s_wcnt[3];
    __syncthreads();
    int ng = s_ng;

    // reduce NSPLIT partials per valid g -> removed bitmap
    if (tid < ng) {
        unsigned long long vmax = 0ull;
        #pragma unroll 4
        for (int s = 0; s < NSPLIT; ++s) {
            unsigned long long v = d_part[((size_t)(b * NSPLIT + s)) * G + tid];
            if (v > vmax) vmax = v;
        }
        if (vmax != 0ull) {
            uint32_t arg = 0xFFFFFFFFu - (uint32_t)(vmax & 0xFFFFFFFFull);
            atomicOr(&s_rem[arg >> 5], 1u << (arg & 31));
        }
    }
    __syncthreads();

    // pass 1: histogram kept keys (+ matched for pos)
    int keptl = 0;
    for (int q = tid; q < P; q += 512) {
        unsigned long long key = src[q];
        if (key != 0ull && !((s_rem[q >> 5] >> (q & 31)) & 1u)) {
            keptl++;
            atomicAdd(&hist[(uint32_t)(key >> 45)], 1u);
            if (isPos) s_matched[d_parg[(size_t)b * P + q]] = 1;
        }
    }
    keptl = __reduce_add_sync(0xFFFFFFFFu, keptl);
    if (lane == 0 && keptl) atomicAdd(&s_kept, keptl);
    __syncthreads();
    if (tid == 0) {
        if (isPos) d_poscount[b] = s_kept;
        else       d_negcount[b] = s_kept;
    }

    // inclusive suffix sum (Hillis-Steele ping-pong)
    for (int i = tid; i < NBINS; i += 512) sfx[i] = hist[i];
    __syncthreads();
    uint32_t* cur = sfx;
    uint32_t* nxt = sfx2;
    for (int d = 1; d < NBINS; d <<= 1) {
        for (int i = tid; i < NBINS; i += 512) {
            uint32_t v = cur[i];
            if (i + d < NBINS) v += cur[i + d];
            nxt[i] = v;
        }
        __syncthreads();
        uint32_t* t = cur; cur = nxt; nxt = t;
    }
    for (int i = tid; i < NBINS; i += 512) {
        if (cur[i] >= (uint32_t)K && (i == NBINS - 1 || cur[i + 1] < (uint32_t)K))
            s_T = i;
    }
    __syncthreads();
    int T = s_T;

    // pass 2: gather candidates (bin >= T, not removed)
    for (int q = tid; q < P; q += 512) {
        unsigned long long key = src[q];
        if (key != 0ull && !((s_rem[q >> 5] >> (q & 31)) & 1u) &&
            (int)(key >> 45) >= T) {
            int pos2 = atomicAdd(&s_cnt, 1);
            if (pos2 < CAND_CAP) { cand[pos2] = key; cand_p[pos2] = (uint32_t)q; }
        }
    }
    __syncthreads();
    int cnt = min(s_cnt, CAND_CAP);

    // rank-by-count (keys distinct via ~p low word): rank r < K -> slot r
    for (int i = tid; i < cnt; i += 512) {
        unsigned long long ki = cand[i];
        int rank = 0;
        for (int j = 0; j < cnt; ++j) rank += (cand[j] > ki) ? 1 : 0;
        if (rank < K) {
            if (isPos) d_posidx[b * POS_CAP + rank] = (int)cand_p[i];
            else       d_negidx[b * R + rank] = (int)cand_p[i];
        }
    }

    // miss (pos block only)
    if (isPos) {
        if (tid < G && gvalid && s_matched[tid] == 0) atomicAdd(&s_miss, 1);
        __syncthreads();
        if (tid == 0) miss_out[b] = (float)s_miss;
    }
}

// ================= K2b: emit outputs (16 blocks) =========================
__global__ void k2b_emit(const float* __restrict__ gt, const int* __restrict__ gcls,
                         const float* __restrict__ pr, float* __restrict__ out) {
    int b = blockIdx.x;
    int s = threadIdx.x;
    if (s >= R) return;

    int np = min(d_poscount[b], POS_CAP);
    int nn = min(R - np, d_negcount[b]);

    float de0 = 0, de1 = 0, de2 = 0, de3 = 0, de4 = 0;
    float c0 = 0, c1 = 0;
    float r0 = 0, r1 = 0, r2 = 0, r3 = 0, r4 = 0;

    bool is_pos = s < np;
    bool is_real = s < np + nn;

    if (is_real) {
        int idx = is_pos ? d_posidx[b * POS_CAP + s] : d_negidx[b * R + (s - np)];
        const float* q = pr + ((size_t)b * P + idx) * 5;
        r0 = q[0]; r1 = q[1]; r2 = q[2]; r3 = q[3]; r4 = 1.0f;
        c1 = 1.0f;
        if (is_pos) {
            int g = d_parg[(size_t)b * P + idx];
            const float* gp = gt + ((size_t)b * G + g) * 5;
            float g0 = gp[0], g1 = gp[1], g2 = gp[2], g3 = gp[3];
            float h = r2 - r0, w = r3 - r1;
            float gh = g2 - g0, gw = g3 - g1;
            float cy = (r2 + r0) * 0.5f, cx = (r3 + r1) * 0.5f;
            float gcy = (g2 + g0) * 0.5f, gcx = (g3 + g1) * 0.5f;
            de0 = ((gcy - cy) / h) / 0.1f;
            de1 = ((gcx - cx) / w) / 0.1f;
            de2 = logf(fmaxf(gh / h, 1e-8f)) / 0.2f;
            de3 = logf(fmaxf(gw / w, 1e-8f)) / 0.2f;
            de4 = 1.0f;
            c0 = (float)gcls[((size_t)b * G + g) * 2 + 0];
        } else {
            de4 = -1.0f;
        }
    }

    size_t sl = (size_t)b * R + s;
    float* dd = out + sl * 5;
    dd[0] = de0; dd[1] = de1; dd[2] = de2; dd[3] = de3; dd[4] = de4;
    float* cc = out + (size_t)B * R * 5 + sl * 2;
    cc[0] = c0; cc[1] = c1;
    float* rr = out + (size_t)B * R * 5 + (size_t)B * R * 2 + sl * 5;
    rr[0] = r0; rr[1] = r1; rr[2] = r2; rr[3] = r3; rr[4] = r4;
}

// ---------------- launch ----------------
extern "C" void kernel_launch(void* const* d_in, const int* in_sizes, int n_in,
                              void* d_out, int out_size) {
    const float* gt = (const float*)d_in[0];
    const int* gcls = (const int*)d_in[1];
    const float* pr = (const float*)d_in[2];
    float* out = (float*)d_out;

    float* miss_out = out + (size_t)B * R * 5 + (size_t)B * R * 2 + (size_t)B * R * 5;

    k1_iou<<<B * NSPLIT, 512>>>(gt, pr);
    k2a_select<<<2 * B, 512>>>(gt, miss_out);
    k2b_emit<<<B, 256>>>(gt, gcls, pr, out);
}

// round 17
// speedup vs baseline: 1.6423x; 1.6423x over previous
#include <cuda_runtime.h>
#include <cstdint>

#define B 16
#define G 128
#define P 8000
#define R 200
#define POS_CAP 66
#define NSPLIT 24
#define CHUNK 334          // 24 * 334 = 8016 >= 8000
#define NBINS 1024
#define CAND_CAP 512
#define NB 384             // persistent blocks: 148 SMs x 3 co-resident

// ---------------- scratch (no allocations allowed) ----------------
__device__ unsigned long long d_gbest[B * G];
__device__ int d_parg[B * P];
__device__ unsigned long long d_poskeys[B * P];
__device__ unsigned long long d_negkeys[B * P];
__device__ int d_poscount[B];
__device__ int d_negcount[B];
__device__ int d_posidx[B * POS_CAP];
__device__ int d_negidx[B * R];
__device__ int d_matched[B * G];
__device__ volatile unsigned d_bar;

// ---------------- threefry2x32 (exact JAX, partitionable path) ----------
__device__ __forceinline__ uint32_t rotl32(uint32_t v, int d) {
    return (v << d) | (v >> (32 - d));
}

__device__ __forceinline__ void threefry(uint32_t k0, uint32_t k1, uint32_t x0,
                                         uint32_t x1, uint32_t& o0, uint32_t& o1) {
    uint32_t ks2 = k0 ^ k1 ^ 0x1BD11BDAu;
    x0 += k0; x1 += k1;
#define TFR(r) { x0 += x1; x1 = rotl32(x1, r); x1 ^= x0; }
    TFR(13) TFR(15) TFR(26) TFR(6)
    x0 += k1; x1 += ks2 + 1u;
    TFR(17) TFR(29) TFR(16) TFR(24)
    x0 += ks2; x1 += k0 + 2u;
    TFR(13) TFR(15) TFR(26) TFR(6)
    x0 += k0; x1 += k1 + 3u;
    TFR(17) TFR(29) TFR(16) TFR(24)
    x0 += k1; x1 += ks2 + 4u;
    TFR(13) TFR(15) TFR(26) TFR(6)
    x0 += ks2; x1 += k0 + 5u;
#undef TFR
    o0 = x0; o1 = x1;
}

__device__ __forceinline__ void batch_keys(int b, uint32_t& k1a, uint32_t& k1b,
                                           uint32_t& k2a, uint32_t& k2b) {
    uint32_t kb0, kb1;
    threefry(0u, 42u, 0u, (uint32_t)b, kb0, kb1);   // split(key(42), 16)[b]
    threefry(kb0, kb1, 0u, 0u, k1a, k1b);           // split(key_b, 2)[0]
    threefry(kb0, kb1, 0u, 1u, k2a, k2b);           // split(key_b, 2)[1]
}

// u = m * 2^-23, m = (o0^o1)>>9: strictly monotonic in m -> sort on mantissa
__device__ __forceinline__ uint32_t umant(uint32_t ka, uint32_t kb, int p) {
    uint32_t a, c;
    threefry(ka, kb, 0u, (uint32_t)p, a, c);
    return (a ^ c) >> 9;
}

// ---------------- software grid barrier ----------------
__device__ __forceinline__ void gsync(unsigned target) {
    __syncthreads();
    if (threadIdx.x == 0) {
        __threadfence();
        atomicAdd((unsigned*)&d_bar, 1u);
        while (d_bar < target) __nanosleep(32);
        __threadfence();
    }
    __syncthreads();
}

// ---------------- init: re-zero accumulators each launch ----------------
__global__ void k_init() {
    int i = blockIdx.x * blockDim.x + threadIdx.x;
    if (i == 0) *(unsigned*)&d_bar = 0u;
    if (i < B * G) { d_gbest[i] = 0ull; d_matched[i] = 0; }
    if (i < B) { d_poscount[i] = 0; d_negcount[i] = 0; }
}

// ---------------- persistent main kernel ----------------
__global__ __launch_bounds__(512, 3)
void k_main(const float* __restrict__ gt, const int* __restrict__ gcls,
            const float* __restrict__ pr, float* __restrict__ out,
            float* __restrict__ miss_out) {
    __shared__ __align__(16) unsigned char s_raw[18432];
    __shared__ int s_wcnt[4], s_woff[4], s_ng;
    __shared__ uint32_t s_rem[16];
    __shared__ int s_T, s_cnt, s_miss;

    int bid = blockIdx.x;
    int tid = threadIdx.x;
    int lane = tid & 31;
    int wid = tid >> 5;

    int b = bid / NSPLIT;
    int split = bid % NSPLIT;
    int pbase = split * CHUNK;

    float4* sg4 = (float4*)s_raw;                               // [132] @0
    float* sga = (float*)(s_raw + 2176);                        // [132]
    int* sglist = (int*)(s_raw + 2720);                         // [132]
    unsigned long long* sbest = (unsigned long long*)(s_raw + 3264);  // [128]

    // ---------- GT load + order-preserving compaction + x4 padding ----------
    {
        bool gvalid = false;
        float a0 = 0, a1 = 0, a2 = 0, a3 = 0;
        if (tid < G) {
            const float* gp = gt + ((size_t)b * G + tid) * 5;
            a0 = gp[0]; a1 = gp[1]; a2 = gp[2]; a3 = gp[3];
            gvalid = (gp[4] != 0.0f);
            sbest[tid] = 0ull;
            unsigned ball = __ballot_sync(0xFFFFFFFFu, gvalid);
            if (lane == 0) s_wcnt[wid] = __popc(ball);
        }
        __syncthreads();
        if (tid == 0) {
            int off = 0;
            for (int w = 0; w < 4; ++w) { s_woff[w] = off; off += s_wcnt[w]; }
            s_ng = off;
        }
        __syncthreads();
        if (tid < G && gvalid) {
            unsigned ball = __ballot_sync(__activemask(), true);
            int rank = s_woff[wid] + __popc(ball & ((1u << lane) - 1u));
            sg4[rank] = make_float4(a0, a1, a2, a3);
            sga[rank] = __fmul_rn(__fsub_rn(a3, a1), __fsub_rn(a2, a0));
            sglist[rank] = tid;
        }
        // pads: degenerate box far outside [0,1.2] -> iou == +0 always
        {
            int ng = s_ng;
            int ng4 = (ng + 3) & ~3;
            if (tid < ng4 - ng) {
                int j = ng + tid;
                sg4[j] = make_float4(4.0f, 4.0f, 4.0f, 4.0f);
                sga[j] = 1.0f;
            }
        }
        __syncthreads();
    }
    int ng = s_ng;
    int ng4 = (ng + 3) & ~3;

    // ---------- phase 1: IoU + per-p argmax + per-g argmax (unroll 4) ------
    int p = pbase + tid;
    bool act = (tid < CHUNK) && (p < P);
    float p0 = 0, p1 = 0, p2 = 0, p3 = 0, ap = 0;
    bool pv = false;
    if (act) {
        const float* pp = pr + ((size_t)b * P + p) * 5;
        p0 = pp[0]; p1 = pp[1]; p2 = pp[2]; p3 = pp[3];
        pv = (pp[4] != 0.0f);
        ap = __fmul_rn(__fsub_rn(p3, p1), __fsub_rn(p2, p0));
    }
    uint32_t vmask = (act && pv) ? 0xFFFFFFFFu : 0u;
    uint32_t wbase = (uint32_t)(pbase + (tid & ~31));

    uint32_t bfv = 0u;   // ford(best valid iou), 0 if none
    int barg = 0;

    for (int i = 0; i < ng4; i += 4) {
        uint32_t fv[4];
        #pragma unroll
        for (int k = 0; k < 4; ++k) {
            float4 gb = sg4[i + k];
            float iw = fmaxf(0.0f, __fsub_rn(fminf(gb.w, p3), fmaxf(gb.y, p1)));
            float ih = fmaxf(0.0f, __fsub_rn(fminf(gb.z, p2), fmaxf(gb.x, p0)));
            float inter = __fmul_rn(iw, ih);
            float denom = __fsub_rn(__fadd_rn(sga[i + k], ap), inter);
            float iou = __fdiv_rn(inter, denom);
            // valid iou >= 0 -> ford(iou) = bits | signbit; invalid -> 0
            fv[k] = (__float_as_uint(iou) | 0x80000000u) & vmask;
            if (fv[k] > bfv) { bfv = fv[k]; barg = i + k; }   // first-index
        }
        uint32_t wmax[4], ball[4];
        #pragma unroll
        for (int k = 0; k < 4; ++k) {
            wmax[k] = __reduce_max_sync(0xFFFFFFFFu, fv[k]);
            ball[k] = __ballot_sync(0xFFFFFFFFu, fv[k] == wmax[k] && wmax[k] != 0u);
        }
        if (lane == 0) {   // one convergence region per 4 g
            #pragma unroll
            for (int k = 0; k < 4; ++k) {
                if (ball[k] != 0u) {
                    uint32_t plow = 0xFFFFFFFFu -
                                    (wbase + (uint32_t)(__ffs(ball[k]) - 1));
                    atomicMax(&sbest[i + k],
                              (((unsigned long long)wmax[k]) << 32) |
                              (unsigned long long)plow);
                }
            }
        }
    }

    __syncthreads();
    if (tid < ng && sbest[tid] != 0ull)
        atomicMax(&d_gbest[(size_t)b * G + sglist[tid]], sbest[tid]);

    // ---------- phase 2 pre: speculative RNG key write (hides barrier) ----
    bool pos = (bfv >= 0xBF000000u);   // ford(0.5f)
    if (act) {
        uint32_t k1a, k1b, k2a, k2b;
        batch_keys(b, k1a, k1b, k2a, k2b);
        unsigned long long pk = 0ull, nk = 0ull;
        if (pv) {
            uint32_t plow = 0xFFFFFFFFu - (uint32_t)p;
            if (pos) {
                pk = (((unsigned long long)umant(k1a, k1b, p)) << 32) |
                     (unsigned long long)plow;
            } else {
                nk = (((unsigned long long)umant(k2a, k2b, p)) << 32) |
                     (unsigned long long)plow;
            }
        }
        size_t bp2 = (size_t)b * P + p;
        d_poskeys[bp2] = pk;
        d_negkeys[bp2] = nk;
    }

    gsync(NB);

    // ---------- phase 2 post: removed fixup, counts, matched, parg --------
    {
        if (tid < 16) s_rem[tid] = 0u;
        __syncthreads();
        if (tid < G) {
            if (gt[((size_t)b * G + tid) * 5 + 4] != 0.0f) {
                unsigned long long key = d_gbest[b * G + tid];
                int arg = (int)(0xFFFFFFFFu - (uint32_t)(key & 0xFFFFFFFFull));
                int rel = arg - pbase;
                if (key != 0ull && rel >= 0 && rel < CHUNK)
                    atomicOr(&s_rem[rel >> 5], 1u << (rel & 31));
            }
        }
        __syncthreads();

        int nposl = 0, nnegl = 0;
        if (act && pv) {
            bool removed = ((s_rem[tid >> 5] >> (tid & 31)) & 1u) != 0;
            size_t bp2 = (size_t)b * P + p;
            if (removed) {
                if (pos) d_poskeys[bp2] = 0ull;
                else     d_negkeys[bp2] = 0ull;
            } else {
                if (pos) {
                    nposl = 1;
                    int gg = sglist[barg];
                    d_matched[b * G + gg] = 1;
                    d_parg[bp2] = gg;
                } else {
                    nnegl = 1;
                }
            }
        }
        nposl = __reduce_add_sync(0xFFFFFFFFu, nposl);
        nnegl = __reduce_add_sync(0xFFFFFFFFu, nnegl);
        if (lane == 0) {
            if (nposl) atomicAdd(&d_poscount[b], nposl);
            if (nnegl) atomicAdd(&d_negcount[b], nnegl);
        }
    }

    gsync(2 * NB);

    // ---------- phase 3: exact top-K select (32 blocks) ----------
    if (bid < 32) {
        uint32_t* hist = (uint32_t*)s_raw;
        uint32_t* sfx = hist + NBINS;
        uint32_t* sfx2 = sfx + NBINS;
        unsigned long long* cand = (unsigned long long*)(sfx2 + NBINS);
        uint32_t* cand_p = (uint32_t*)(cand + CAND_CAP);

        int sb = bid >> 1;
        bool isPos = ((bid & 1) == 0);
        int K = isPos ? POS_CAP : R;
        const unsigned long long* src =
            isPos ? (d_poskeys + (size_t)sb * P) : (d_negkeys + (size_t)sb * P);

        for (int i = tid; i < NBINS; i += 512) hist[i] = 0u;
        if (tid == 0) { s_T = 0; s_cnt = 0; }
        __syncthreads();

        for (int q = tid; q < P; q += 512) {
            unsigned long long key = src[q];
            if (key != 0ull) atomicAdd(&hist[(uint32_t)(key >> 45)], 1u);
        }
        __syncthreads();

        for (int i = tid; i < NBINS; i += 512) sfx[i] = hist[i];
        __syncthreads();
        uint32_t* cur = sfx;
        uint32_t* nxt = sfx2;
        for (int d = 1; d < NBINS; d <<= 1) {
            for (int i = tid; i < NBINS; i += 512) {
                uint32_t v = cur[i];
                if (i + d < NBINS) v += cur[i + d];
                nxt[i] = v;
            }
            __syncthreads();
            uint32_t* t = cur; cur = nxt; nxt = t;
        }
        for (int i = tid; i < NBINS; i += 512) {
            if (cur[i] >= (uint32_t)K && (i == NBINS - 1 || cur[i + 1] < (uint32_t)K))
                s_T = i;
        }
        __syncthreads();
        int T = s_T;

        for (int q = tid; q < P; q += 512) {
            unsigned long long key = src[q];
            if (key != 0ull && (int)(key >> 45) >= T) {
                int pos2 = atomicAdd(&s_cnt, 1);
                if (pos2 < CAND_CAP) { cand[pos2] = key; cand_p[pos2] = (uint32_t)q; }
            }
        }
        __syncthreads();
        int cnt = min(s_cnt, CAND_CAP);

        for (int i = tid; i < cnt; i += 512) {
            unsigned long long ki = cand[i];
            int rank = 0;
            for (int j = 0; j < cnt; ++j) rank += (cand[j] > ki) ? 1 : 0;
            if (rank < K) {
                if (isPos) d_posidx[sb * POS_CAP + rank] = (int)cand_p[i];
                else       d_negidx[sb * R + rank] = (int)cand_p[i];
            }
        }
    }

    gsync(3 * NB);

    // ---------- phase 4: emit outputs (16 blocks) ----------
    if (bid >= B) return;
    int eb = bid;

    if (tid == 0) s_miss = 0;
    __syncthreads();
    if (tid < G) {
        if (gt[((size_t)eb * G + tid) * 5 + 4] != 0.0f && d_matched[eb * G + tid] == 0)
            atomicAdd(&s_miss, 1);
    }

    if (tid < R) {
        int s = tid;
        int np = min(d_poscount[eb], POS_CAP);
        int nn = min(R - np, d_negcount[eb]);

        float de0 = 0, de1 = 0, de2 = 0, de3 = 0, de4 = 0;
        float c0 = 0, c1 = 0;
        float r0 = 0, r1 = 0, r2 = 0, r3 = 0, r4 = 0;

        bool is_pos = s < np;
        bool is_real = s < np + nn;

        if (is_real) {
            int idx = is_pos ? d_posidx[eb * POS_CAP + s] : d_negidx[eb * R + (s - np)];
            const float* q = pr + ((size_t)eb * P + idx) * 5;
            r0 = q[0]; r1 = q[1]; r2 = q[2]; r3 = q[3]; r4 = 1.0f;
            c1 = 1.0f;
            if (is_pos) {
                int g = d_parg[(size_t)eb * P + idx];
                const float* gp = gt + ((size_t)eb * G + g) * 5;
                float g0 = gp[0], g1 = gp[1], g2 = gp[2], g3 = gp[3];
                float h = r2 - r0, w = r3 - r1;
                float gh = g2 - g0, gw = g3 - g1;
                float cy = (r2 + r0) * 0.5f, cx = (r3 + r1) * 0.5f;
                float gcy = (g2 + g0) * 0.5f, gcx = (g3 + g1) * 0.5f;
                de0 = ((gcy - cy) / h) / 0.1f;
                de1 = ((gcx - cx) / w) / 0.1f;
                de2 = logf(fmaxf(gh / h, 1e-8f)) / 0.2f;
                de3 = logf(fmaxf(gw / w, 1e-8f)) / 0.2f;
                de4 = 1.0f;
                c0 = (float)gcls[((size_t)eb * G + g) * 2 + 0];
            } else {
                de4 = -1.0f;
            }
        }

        size_t sl = (size_t)eb * R + s;
        float* dd = out + sl * 5;
        dd[0] = de0; dd[1] = de1; dd[2] = de2; dd[3] = de3; dd[4] = de4;
        float* cc = out + (size_t)B * R * 5 + sl * 2;
        cc[0] = c0; cc[1] = c1;
        float* rr = out + (size_t)B * R * 5 + (size_t)B * R * 2 + sl * 5;
        rr[0] = r0; rr[1] = r1; rr[2] = r2; rr[3] = r3; rr[4] = r4;
    }

    __syncthreads();
    if (tid == 0) miss_out[eb] = (float)s_miss;
}

// ---------------- launch ----------------
extern "C" void kernel_launch(void* const* d_in, const int* in_sizes, int n_in,
                              void* d_out, int out_size) {
    const float* gt = (const float*)d_in[0];
    const int* gcls = (const int*)d_in[1];
    const float* pr = (const float*)d_in[2];
    float* out = (float*)d_out;

    float* miss_out = out + (size_t)B * R * 5 + (size_t)B * R * 2 + (size_t)B * R * 5;

    k_init<<<8, 256>>>();
    k_main<<<NB, 512>>>(gt, gcls, pr, out, miss_out);
}